// round 2
// baseline (speedup 1.0000x reference)
#include <cuda_runtime.h>
#include <cstdint>
#include <math.h>

// ---------------------------------------------------------------------------
// Scratch (static device globals — no runtime allocation)
// ---------------------------------------------------------------------------
__device__ float g_h0 [8192u * 2048u];   // 64 MB
__device__ float g_pre[8192u * 2048u];   // 64 MB
__device__ float g_err[8192u * 4096u];   // 128 MB
__device__ float g_prec2[4096];

// ---------------------------------------------------------------------------
// Helpers
// ---------------------------------------------------------------------------
__device__ __forceinline__ uint32_t f2tf32(float x) {
    uint32_t r;
    asm("cvt.rna.tf32.f32 %0, %1;" : "=r"(r) : "f"(x));
    return r;
}

__device__ __forceinline__ void mma_tf32(float* c, const uint32_t* a, const uint32_t* b) {
    asm volatile(
        "mma.sync.aligned.m16n8k8.row.col.f32.tf32.tf32.f32 "
        "{%0,%1,%2,%3}, {%4,%5,%6,%7}, {%8,%9}, {%0,%1,%2,%3};\n"
        : "+f"(c[0]), "+f"(c[1]), "+f"(c[2]), "+f"(c[3])
        : "r"(a[0]), "r"(a[1]), "r"(a[2]), "r"(a[3]), "r"(b[0]), "r"(b[1]));
}

// ---------------------------------------------------------------------------
// prec2 = softplus(log_prec)^2
// ---------------------------------------------------------------------------
__global__ void prec2_kernel(const float* __restrict__ lp, float* __restrict__ out, int n) {
    int i = blockIdx.x * blockDim.x + threadIdx.x;
    if (i < n) {
        float v = lp[i];
        float sp = (v > 20.f) ? v : log1pf(expf(v));
        out[i] = sp * sp;
    }
}

// ---------------------------------------------------------------------------
// Row LayerNorm: dst = (src - mu) * rsqrt(var + eps) * gamma + beta
// One block (256 threads) per row; row staged in registers.
// ---------------------------------------------------------------------------
template <int H>
__global__ void __launch_bounds__(256) ln_kernel(
    const float* __restrict__ src, float* __restrict__ dst,
    const float* __restrict__ gam, const float* __restrict__ bet)
{
    constexpr int V = H / (4 * 256);   // float4 per thread (H=2048 -> 2, H=1024 -> 1)
    int row = blockIdx.x;
    const float4* s = reinterpret_cast<const float4*>(src + (size_t)row * H);
    float4* d = reinterpret_cast<float4*>(dst + (size_t)row * H);

    float4 v[V];
    float sum = 0.f, sq = 0.f;
#pragma unroll
    for (int i = 0; i < V; i++) {
        v[i] = s[threadIdx.x + i * 256];
        sum += v[i].x + v[i].y + v[i].z + v[i].w;
        sq  += v[i].x * v[i].x + v[i].y * v[i].y + v[i].z * v[i].z + v[i].w * v[i].w;
    }
#pragma unroll
    for (int o = 16; o > 0; o >>= 1) {
        sum += __shfl_xor_sync(0xffffffffu, sum, o);
        sq  += __shfl_xor_sync(0xffffffffu, sq,  o);
    }
    __shared__ float sS[8], sQ[8];
    int w = threadIdx.x >> 5, l = threadIdx.x & 31;
    if (l == 0) { sS[w] = sum; sQ[w] = sq; }
    __syncthreads();
    if (threadIdx.x == 0) {
        float ts = 0.f, tq = 0.f;
#pragma unroll
        for (int i = 0; i < 8; i++) { ts += sS[i]; tq += sQ[i]; }
        sS[0] = ts; sQ[0] = tq;
    }
    __syncthreads();
    float mu  = sS[0] * (1.f / H);
    float var = sQ[0] * (1.f / H) - mu * mu;
    float inv = rsqrtf(var + 1e-5f);
#pragma unroll
    for (int i = 0; i < V; i++) {
        int ci = threadIdx.x + i * 256;
        float4 g4 = reinterpret_cast<const float4*>(gam)[ci];
        float4 b4 = reinterpret_cast<const float4*>(bet)[ci];
        float4 o;
        o.x = (v[i].x - mu) * inv * g4.x + b4.x;
        o.y = (v[i].y - mu) * inv * g4.y + b4.y;
        o.z = (v[i].z - mu) * inv * g4.z + b4.z;
        o.w = (v[i].w - mu) * inv * g4.w + b4.w;
        d[ci] = o;
    }
}

// ---------------------------------------------------------------------------
// TF32 tensor-core GEMM, 128x128x16 tiles, 256 threads (2x4 warps, 64x32/warp).
//   C[M,N] = A[M,K] * B  where  BT=true : B(k,n) = W[n,k]   (W row-major [N,K])
//                               BT=false: B(k,n) = W[k,n]   (W row-major [K,N])
// Epilogue MODE: 0: out = acc + bias[n]
//               1: out = (X[m,n] - (acc + bias[n])) * prec2[n]
//               2: out = X[m,n] + 0.2f * acc
// Requires M%128==0, N%128==0, K%16==0 (true for all shapes here).
// ---------------------------------------------------------------------------
template <bool BT, int MODE>
__global__ void __launch_bounds__(256) gemm_tf32(
    const float* __restrict__ A, const float* __restrict__ W,
    const float* __restrict__ bias, const float* __restrict__ X,
    const float* __restrict__ prec2, float* __restrict__ OUT,
    int M, int N, int K)
{
    constexpr int BM = 128, BN = 128, BK = 16;
    // [k][m] layout, stride 136 (== 8 mod 32) -> conflict-free mma fragment LDS
    __shared__ __align__(16) float As[2][BK][BM + 8];
    __shared__ __align__(16) float Bs[2][BK][BM + 8];

    const int tid  = threadIdx.x;
    const int lane = tid & 31;
    const int warp = tid >> 5;
    const int wm = warp >> 2;          // 0..1
    const int wn = warp & 3;           // 0..3
    const int gid = lane >> 2, tig = lane & 3;
    const int M0 = blockIdx.y * BM, N0 = blockIdx.x * BN;

    float acc[4][4][4];
#pragma unroll
    for (int i = 0; i < 4; i++)
#pragma unroll
        for (int j = 0; j < 4; j++)
#pragma unroll
            for (int k = 0; k < 4; k++) acc[i][j][k] = 0.f;

    // global-load thread mapping (one row per thread; 2 float4 along K)
    const int am = tid & 127;          // tile row (A), or W row (BT)
    const int aj = tid >> 7;           // 0..1 -> kvec j and j+2
    const int bk = tid >> 5;           // 0..7 (NN path): W k-row, +8 second half
    const int bnv = tid & 31;          // NN path: n float4 index

    const int KT = K / BK;
    float4 aReg[2], bReg[2];

    auto ldg = [&](int kt) {
        const float* Ab = A + (size_t)(M0 + am) * K + kt * BK;
        aReg[0] = *(const float4*)(Ab + aj * 4);
        aReg[1] = *(const float4*)(Ab + (aj + 2) * 4);
        if (BT) {
            const float* Wb = W + (size_t)(N0 + am) * K + kt * BK;
            bReg[0] = *(const float4*)(Wb + aj * 4);
            bReg[1] = *(const float4*)(Wb + (aj + 2) * 4);
        } else {
            const float* Wb = W + (size_t)(kt * BK) * N + N0;
            bReg[0] = *(const float4*)(Wb + (size_t)bk * N + bnv * 4);
            bReg[1] = *(const float4*)(Wb + (size_t)(bk + 8) * N + bnv * 4);
        }
    };

    auto sts = [&](int buf) {
#pragma unroll
        for (int h = 0; h < 2; h++) {
            int kk = (h ? aj + 2 : aj) * 4;
            const float* p = (const float*)&aReg[h];
#pragma unroll
            for (int c = 0; c < 4; c++)
                As[buf][kk + c][am] = __uint_as_float(f2tf32(p[c]));
        }
        if (BT) {
#pragma unroll
            for (int h = 0; h < 2; h++) {
                int kk = (h ? aj + 2 : aj) * 4;
                const float* p = (const float*)&bReg[h];
#pragma unroll
                for (int c = 0; c < 4; c++)
                    Bs[buf][kk + c][am] = __uint_as_float(f2tf32(p[c]));
            }
        } else {
#pragma unroll
            for (int h = 0; h < 2; h++) {
                int kk = h ? bk + 8 : bk;
                const float* p = (const float*)&bReg[h];
                float4 v;
                v.x = __uint_as_float(f2tf32(p[0]));
                v.y = __uint_as_float(f2tf32(p[1]));
                v.z = __uint_as_float(f2tf32(p[2]));
                v.w = __uint_as_float(f2tf32(p[3]));
                *(float4*)&Bs[buf][kk][bnv * 4] = v;
            }
        }
    };

    ldg(0);
    sts(0);
    __syncthreads();

    for (int kt = 0; kt < KT; kt++) {
        const int cur = kt & 1;
        if (kt + 1 < KT) ldg(kt + 1);

#pragma unroll
        for (int ks = 0; ks < 2; ks++) {
            const int k0 = ks * 8;
            uint32_t af[4][4], bf[4][2];
#pragma unroll
            for (int mm = 0; mm < 4; mm++) {
                int r = wm * 64 + mm * 16 + gid;
                af[mm][0] = __float_as_uint(As[cur][k0 + tig    ][r]);
                af[mm][1] = __float_as_uint(As[cur][k0 + tig    ][r + 8]);
                af[mm][2] = __float_as_uint(As[cur][k0 + tig + 4][r]);
                af[mm][3] = __float_as_uint(As[cur][k0 + tig + 4][r + 8]);
            }
#pragma unroll
            for (int nn = 0; nn < 4; nn++) {
                int cN = wn * 32 + nn * 8 + gid;
                bf[nn][0] = __float_as_uint(Bs[cur][k0 + tig    ][cN]);
                bf[nn][1] = __float_as_uint(Bs[cur][k0 + tig + 4][cN]);
            }
#pragma unroll
            for (int mm = 0; mm < 4; mm++)
#pragma unroll
                for (int nn = 0; nn < 4; nn++)
                    mma_tf32(acc[mm][nn], af[mm], bf[nn]);
        }

        if (kt + 1 < KT) sts(cur ^ 1);
        __syncthreads();
    }

    // epilogue
#pragma unroll
    for (int mm = 0; mm < 4; mm++) {
        int r0 = M0 + wm * 64 + mm * 16 + gid;
#pragma unroll
        for (int nn = 0; nn < 4; nn++) {
            int c = N0 + wn * 32 + nn * 8 + 2 * tig;
#pragma unroll
            for (int h = 0; h < 2; h++) {
                int r = r0 + h * 8;
                size_t off = (size_t)r * N + c;
                float v0 = acc[mm][nn][2 * h + 0];
                float v1 = acc[mm][nn][2 * h + 1];
                if (MODE == 0) {
                    v0 += bias[c];
                    v1 += bias[c + 1];
                } else if (MODE == 1) {
                    float2 xv = *(const float2*)(X + off);
                    v0 = (xv.x - (v0 + bias[c]))     * prec2[c];
                    v1 = (xv.y - (v1 + bias[c + 1])) * prec2[c + 1];
                } else {
                    float2 xv = *(const float2*)(X + off);
                    v0 = xv.x + 0.2f * v0;
                    v1 = xv.y + 0.2f * v1;
                }
                float2 o; o.x = v0; o.y = v1;
                *(float2*)(OUT + off) = o;
            }
        }
    }
}

// ---------------------------------------------------------------------------
// Launch sequence (graph-capturable: kernel launches only)
// ---------------------------------------------------------------------------
extern "C" void kernel_launch(void* const* d_in, const int* in_sizes, int n_in,
                              void* d_out, int out_size)
{
    const float* x      = (const float*)d_in[0];
    const float* gen_w0 = (const float*)d_in[1];
    const float* gen_b0 = (const float*)d_in[2];
    const float* rec_w0 = (const float*)d_in[3];
    const float* rec_b0 = (const float*)d_in[4];
    const float* lp0    = (const float*)d_in[5];
    const float* ln_g0  = (const float*)d_in[6];
    const float* ln_b0  = (const float*)d_in[7];
    const float* gen_w1 = (const float*)d_in[8];
    const float* gen_b1 = (const float*)d_in[9];
    const float* rec_w1 = (const float*)d_in[10];
    const float* rec_b1 = (const float*)d_in[11];
    const float* lp1    = (const float*)d_in[12];
    const float* ln_g1  = (const float*)d_in[13];
    const float* ln_b1  = (const float*)d_in[14];
    float* out = (float*)d_out;

    float *h0, *pre, *err, *pr2;
    cudaGetSymbolAddress((void**)&h0,  g_h0);
    cudaGetSymbolAddress((void**)&pre, g_pre);
    cudaGetSymbolAddress((void**)&err, g_err);
    cudaGetSymbolAddress((void**)&pr2, g_prec2);

    const int B = 8192;
    dim3 blk(256);

    // ---- layer 0: in=4096, hid=2048 ----
    prec2_kernel<<<4096 / 256, blk>>>(lp0, pr2, 4096);
    gemm_tf32<true, 0><<<dim3(2048 / 128, B / 128), blk>>>(
        x, rec_w0, rec_b0, nullptr, nullptr, pre, B, 2048, 4096);
    ln_kernel<2048><<<B, blk>>>(pre, h0, ln_g0, ln_b0);
    for (int it = 0; it < 3; it++) {
        gemm_tf32<true, 1><<<dim3(4096 / 128, B / 128), blk>>>(
            h0, gen_w0, gen_b0, x, pr2, err, B, 4096, 2048);
        gemm_tf32<false, 2><<<dim3(2048 / 128, B / 128), blk>>>(
            err, gen_w0, nullptr, h0, nullptr, pre, B, 2048, 4096);
        ln_kernel<2048><<<B, blk>>>(pre, h0, ln_g0, ln_b0);
    }

    // ---- layer 1: in=2048, hid=1024 ----
    prec2_kernel<<<2048 / 256, blk>>>(lp1, pr2, 2048);
    gemm_tf32<true, 0><<<dim3(1024 / 128, B / 128), blk>>>(
        h0, rec_w1, rec_b1, nullptr, nullptr, pre, B, 1024, 2048);
    ln_kernel<1024><<<B, blk>>>(pre, out, ln_g1, ln_b1);
    for (int it = 0; it < 3; it++) {
        gemm_tf32<true, 1><<<dim3(2048 / 128, B / 128), blk>>>(
            out, gen_w1, gen_b1, h0, pr2, err, B, 2048, 1024);
        gemm_tf32<false, 2><<<dim3(1024 / 128, B / 128), blk>>>(
            err, gen_w1, nullptr, out, nullptr, pre, B, 1024, 2048);
        ln_kernel<1024><<<B, blk>>>(pre, out, ln_g1, ln_b1);
    }
}

// round 3
// speedup vs baseline: 1.6520x; 1.6520x over previous
#include <cuda_runtime.h>
#include <cstdint>
#include <math.h>

// ---------------------------------------------------------------------------
// Scratch (static device globals — no runtime allocation)
// ---------------------------------------------------------------------------
__device__ float g_h0 [8192u * 2048u];   // 64 MB
__device__ float g_pre[8192u * 2048u];   // 64 MB
__device__ float g_err[8192u * 4096u];   // 128 MB
__device__ float g_prec2[4096];

// ---------------------------------------------------------------------------
// Helpers
// ---------------------------------------------------------------------------
__device__ __forceinline__ uint32_t f2tf32(float x) {
    uint32_t r;
    asm("cvt.rna.tf32.f32 %0, %1;" : "=r"(r) : "f"(x));
    return r;
}

__device__ __forceinline__ void mma_tf32(float* c, const uint32_t* a, const uint32_t* b) {
    asm volatile(
        "mma.sync.aligned.m16n8k8.row.col.f32.tf32.tf32.f32 "
        "{%0,%1,%2,%3}, {%4,%5,%6,%7}, {%8,%9}, {%0,%1,%2,%3};\n"
        : "+f"(c[0]), "+f"(c[1]), "+f"(c[2]), "+f"(c[3])
        : "r"(a[0]), "r"(a[1]), "r"(a[2]), "r"(a[3]), "r"(b[0]), "r"(b[1]));
}

__device__ __forceinline__ void cp16(uint32_t dst_smem, const void* src) {
    asm volatile("cp.async.cg.shared.global [%0], [%1], 16;" :: "r"(dst_smem), "l"(src));
}
__device__ __forceinline__ void cp_commit() {
    asm volatile("cp.async.commit_group;");
}
template <int N>
__device__ __forceinline__ void cp_wait() {
    asm volatile("cp.async.wait_group %0;" :: "n"(N));
}

// ---------------------------------------------------------------------------
// prec2 = softplus(log_prec)^2
// ---------------------------------------------------------------------------
__global__ void prec2_kernel(const float* __restrict__ lp, float* __restrict__ out, int n) {
    int i = blockIdx.x * blockDim.x + threadIdx.x;
    if (i < n) {
        float v = lp[i];
        float sp = (v > 20.f) ? v : log1pf(expf(v));
        out[i] = sp * sp;
    }
}

// ---------------------------------------------------------------------------
// Row LayerNorm: dst = (src - mu) * rsqrt(var + eps) * gamma + beta
// ---------------------------------------------------------------------------
template <int H>
__global__ void __launch_bounds__(256) ln_kernel(
    const float* __restrict__ src, float* __restrict__ dst,
    const float* __restrict__ gam, const float* __restrict__ bet)
{
    constexpr int V = H / (4 * 256);
    int row = blockIdx.x;
    const float4* s = reinterpret_cast<const float4*>(src + (size_t)row * H);
    float4* d = reinterpret_cast<float4*>(dst + (size_t)row * H);

    float4 v[V];
    float sum = 0.f, sq = 0.f;
#pragma unroll
    for (int i = 0; i < V; i++) {
        v[i] = s[threadIdx.x + i * 256];
        sum += v[i].x + v[i].y + v[i].z + v[i].w;
        sq  += v[i].x * v[i].x + v[i].y * v[i].y + v[i].z * v[i].z + v[i].w * v[i].w;
    }
#pragma unroll
    for (int o = 16; o > 0; o >>= 1) {
        sum += __shfl_xor_sync(0xffffffffu, sum, o);
        sq  += __shfl_xor_sync(0xffffffffu, sq,  o);
    }
    __shared__ float sS[8], sQ[8];
    int w = threadIdx.x >> 5, l = threadIdx.x & 31;
    if (l == 0) { sS[w] = sum; sQ[w] = sq; }
    __syncthreads();
    if (threadIdx.x == 0) {
        float ts = 0.f, tq = 0.f;
#pragma unroll
        for (int i = 0; i < 8; i++) { ts += sS[i]; tq += sQ[i]; }
        sS[0] = ts; sQ[0] = tq;
    }
    __syncthreads();
    float mu  = sS[0] * (1.f / H);
    float var = sQ[0] * (1.f / H) - mu * mu;
    float inv = rsqrtf(var + 1e-5f);
#pragma unroll
    for (int i = 0; i < V; i++) {
        int ci = threadIdx.x + i * 256;
        float4 g4 = reinterpret_cast<const float4*>(gam)[ci];
        float4 b4 = reinterpret_cast<const float4*>(bet)[ci];
        float4 o;
        o.x = (v[i].x - mu) * inv * g4.x + b4.x;
        o.y = (v[i].y - mu) * inv * g4.y + b4.y;
        o.z = (v[i].z - mu) * inv * g4.z + b4.z;
        o.w = (v[i].w - mu) * inv * g4.w + b4.w;
        d[ci] = o;
    }
}

// ---------------------------------------------------------------------------
// TF32 tensor-core GEMM, 128x128 tile, BK=16, 4-stage cp.async pipeline.
// Raw fp32 staged in smem; cvt.rna.tf32 applied at fragment load.
//   BT=true : B(k,n) = W[n,k]   (W row-major [N,K])
//   BT=false: B(k,n) = W[k,n]   (W row-major [K,N])
// MODE 0: out = acc + bias[n]
// MODE 1: out = (X - (acc + bias[n])) * prec2[n]
// MODE 2: out = X + 0.2f * acc
// Requires M%128==0, N%128==0, K%16==0.
// ---------------------------------------------------------------------------
template <bool BT, int MODE>
__global__ void __launch_bounds__(256, 2) gemm_tf32(
    const float* __restrict__ A, const float* __restrict__ W,
    const float* __restrict__ bias, const float* __restrict__ X,
    const float* __restrict__ prec2, float* __restrict__ OUT,
    int M, int N, int K)
{
    constexpr int S    = 4;      // pipeline stages
    constexpr int AROW = 20;     // 16 k-floats + 4 pad (80B rows, 16B aligned)
    constexpr int BRN  = 136;    // NN path: 128 n-floats + 8 pad (544B rows)
    constexpr int A_FLOATS = 128 * AROW;            // per stage
    constexpr int B_FLOATS = BT ? 128 * AROW : 16 * BRN;

    extern __shared__ float sm[];
    float* Asm = sm;                       // [S][128][AROW]
    float* Bsm = sm + S * A_FLOATS;        // [S][128][AROW] or [S][16][BRN]

    const uint32_t sA = (uint32_t)__cvta_generic_to_shared(Asm);
    const uint32_t sB = (uint32_t)__cvta_generic_to_shared(Bsm);

    const int tid  = threadIdx.x;
    const int lane = tid & 31;
    const int warp = tid >> 5;
    const int wm = warp >> 2;          // 0..1
    const int wn = warp & 3;           // 0..3
    const int gid = lane >> 2, tig = lane & 3;
    const int M0 = blockIdx.y * 128, N0 = blockIdx.x * 128;

    float acc[4][4][4];
#pragma unroll
    for (int i = 0; i < 4; i++)
#pragma unroll
        for (int j = 0; j < 4; j++)
#pragma unroll
            for (int k = 0; k < 4; k++) acc[i][j][k] = 0.f;

    const int KT = K / 16;

    // async copy of one stage (512 16B-chunks each for A and B; 2 per thread)
    auto ldgsts = [&](int kt, int st) {
#pragma unroll
        for (int i = 0; i < 2; i++) {
            int c   = tid + 256 * i;
            int row = c >> 2, kv = c & 3;          // row 0..127, kvec 0..3
            cp16(sA + (uint32_t)(st * A_FLOATS + row * AROW + kv * 4) * 4u,
                 A + (size_t)(M0 + row) * K + kt * 16 + kv * 4);
        }
        if (BT) {
#pragma unroll
            for (int i = 0; i < 2; i++) {
                int c   = tid + 256 * i;
                int row = c >> 2, kv = c & 3;
                cp16(sB + (uint32_t)(st * B_FLOATS + row * AROW + kv * 4) * 4u,
                     W + (size_t)(N0 + row) * K + kt * 16 + kv * 4);
            }
        } else {
#pragma unroll
            for (int i = 0; i < 2; i++) {
                int c  = tid + 256 * i;
                int kr = c >> 5, nv = c & 31;      // k-row 0..15, nvec 0..31
                cp16(sB + (uint32_t)(st * B_FLOATS + kr * BRN + nv * 4) * 4u,
                     W + (size_t)(kt * 16 + kr) * N + N0 + nv * 4);
            }
        }
    };

    // prologue: fill S-1 stages
#pragma unroll
    for (int s = 0; s < S - 1; s++) {
        ldgsts(s, s);
        cp_commit();
    }

    for (int kt = 0; kt < KT; kt++) {
        cp_wait<S - 2>();
        __syncthreads();

        int nk = kt + S - 1;
        if (nk < KT) ldgsts(nk, nk & (S - 1));
        cp_commit();

        const int cur = kt & (S - 1);
        const float* Ast = Asm + cur * A_FLOATS;
        const float* Bst = Bsm + cur * B_FLOATS;

#pragma unroll
        for (int ks = 0; ks < 2; ks++) {
            const int k0 = ks * 8;
            uint32_t af[4][4], bf[4][2];
#pragma unroll
            for (int mm = 0; mm < 4; mm++) {
                int r = wm * 64 + mm * 16 + gid;
                af[mm][0] = f2tf32(Ast[(r    ) * AROW + k0 + tig    ]);
                af[mm][1] = f2tf32(Ast[(r + 8) * AROW + k0 + tig    ]);
                af[mm][2] = f2tf32(Ast[(r    ) * AROW + k0 + tig + 4]);
                af[mm][3] = f2tf32(Ast[(r + 8) * AROW + k0 + tig + 4]);
            }
#pragma unroll
            for (int nn = 0; nn < 4; nn++) {
                int cN = wn * 32 + nn * 8 + gid;
                if (BT) {
                    bf[nn][0] = f2tf32(Bst[cN * AROW + k0 + tig    ]);
                    bf[nn][1] = f2tf32(Bst[cN * AROW + k0 + tig + 4]);
                } else {
                    bf[nn][0] = f2tf32(Bst[(k0 + tig    ) * BRN + cN]);
                    bf[nn][1] = f2tf32(Bst[(k0 + tig + 4) * BRN + cN]);
                }
            }
#pragma unroll
            for (int mm = 0; mm < 4; mm++)
#pragma unroll
                for (int nn = 0; nn < 4; nn++)
                    mma_tf32(acc[mm][nn], af[mm], bf[nn]);
        }
        __syncthreads();
    }

    // epilogue
#pragma unroll
    for (int mm = 0; mm < 4; mm++) {
        int r0 = M0 + wm * 64 + mm * 16 + gid;
#pragma unroll
        for (int nn = 0; nn < 4; nn++) {
            int c = N0 + wn * 32 + nn * 8 + 2 * tig;
#pragma unroll
            for (int h = 0; h < 2; h++) {
                int r = r0 + h * 8;
                size_t off = (size_t)r * N + c;
                float v0 = acc[mm][nn][2 * h + 0];
                float v1 = acc[mm][nn][2 * h + 1];
                if (MODE == 0) {
                    v0 += bias[c];
                    v1 += bias[c + 1];
                } else if (MODE == 1) {
                    float2 xv = *(const float2*)(X + off);
                    v0 = (xv.x - (v0 + bias[c]))     * prec2[c];
                    v1 = (xv.y - (v1 + bias[c + 1])) * prec2[c + 1];
                } else {
                    float2 xv = *(const float2*)(X + off);
                    v0 = xv.x + 0.2f * v0;
                    v1 = xv.y + 0.2f * v1;
                }
                float2 o; o.x = v0; o.y = v1;
                *(float2*)(OUT + off) = o;
            }
        }
    }
}

// ---------------------------------------------------------------------------
// Launch sequence (graph-capturable: kernel launches only)
// ---------------------------------------------------------------------------
extern "C" void kernel_launch(void* const* d_in, const int* in_sizes, int n_in,
                              void* d_out, int out_size)
{
    const float* x      = (const float*)d_in[0];
    const float* gen_w0 = (const float*)d_in[1];
    const float* gen_b0 = (const float*)d_in[2];
    const float* rec_w0 = (const float*)d_in[3];
    const float* rec_b0 = (const float*)d_in[4];
    const float* lp0    = (const float*)d_in[5];
    const float* ln_g0  = (const float*)d_in[6];
    const float* ln_b0  = (const float*)d_in[7];
    const float* gen_w1 = (const float*)d_in[8];
    const float* gen_b1 = (const float*)d_in[9];
    const float* rec_w1 = (const float*)d_in[10];
    const float* rec_b1 = (const float*)d_in[11];
    const float* lp1    = (const float*)d_in[12];
    const float* ln_g1  = (const float*)d_in[13];
    const float* ln_b1  = (const float*)d_in[14];
    float* out = (float*)d_out;

    float *h0, *pre, *err, *pr2;
    cudaGetSymbolAddress((void**)&h0,  g_h0);
    cudaGetSymbolAddress((void**)&pre, g_pre);
    cudaGetSymbolAddress((void**)&err, g_err);
    cudaGetSymbolAddress((void**)&pr2, g_prec2);

    // dynamic smem sizes: BT = 4*(128*20)*2 floats = 80 KB; NN = 4*(128*20 + 16*136) floats
    const int SM_BT = 4 * 128 * 20 * 2 * 4;              // 81920 B
    const int SM_NN = 4 * (128 * 20 + 16 * 136) * 4;     // 75776 B
    // First call happens outside graph capture; later calls are idempotent no-ops.
    cudaFuncSetAttribute(gemm_tf32<true, 0>,  cudaFuncAttributeMaxDynamicSharedMemorySize, SM_BT);
    cudaFuncSetAttribute(gemm_tf32<true, 1>,  cudaFuncAttributeMaxDynamicSharedMemorySize, SM_BT);
    cudaFuncSetAttribute(gemm_tf32<false, 2>, cudaFuncAttributeMaxDynamicSharedMemorySize, SM_NN);

    const int B = 8192;
    dim3 blk(256);

    // ---- layer 0: in=4096, hid=2048 ----
    prec2_kernel<<<4096 / 256, blk>>>(lp0, pr2, 4096);
    gemm_tf32<true, 0><<<dim3(2048 / 128, B / 128), blk, SM_BT>>>(
        x, rec_w0, rec_b0, nullptr, nullptr, pre, B, 2048, 4096);
    ln_kernel<2048><<<B, blk>>>(pre, h0, ln_g0, ln_b0);
    for (int it = 0; it < 3; it++) {
        gemm_tf32<true, 1><<<dim3(4096 / 128, B / 128), blk, SM_BT>>>(
            h0, gen_w0, gen_b0, x, pr2, err, B, 4096, 2048);
        gemm_tf32<false, 2><<<dim3(2048 / 128, B / 128), blk, SM_NN>>>(
            err, gen_w0, nullptr, h0, nullptr, pre, B, 2048, 4096);
        ln_kernel<2048><<<B, blk>>>(pre, h0, ln_g0, ln_b0);
    }

    // ---- layer 1: in=2048, hid=1024 ----
    prec2_kernel<<<2048 / 256, blk>>>(lp1, pr2, 2048);
    gemm_tf32<true, 0><<<dim3(1024 / 128, B / 128), blk, SM_BT>>>(
        h0, rec_w1, rec_b1, nullptr, nullptr, pre, B, 1024, 2048);
    ln_kernel<1024><<<B, blk>>>(pre, out, ln_g1, ln_b1);
    for (int it = 0; it < 3; it++) {
        gemm_tf32<true, 1><<<dim3(2048 / 128, B / 128), blk, SM_BT>>>(
            out, gen_w1, gen_b1, h0, pr2, err, B, 2048, 1024);
        gemm_tf32<false, 2><<<dim3(1024 / 128, B / 128), blk, SM_NN>>>(
            err, gen_w1, nullptr, out, nullptr, pre, B, 1024, 2048);
        ln_kernel<1024><<<B, blk>>>(pre, out, ln_g1, ln_b1);
    }
}

// round 4
// speedup vs baseline: 1.8877x; 1.1426x over previous
#include <cuda_runtime.h>
#include <cstdint>
#include <math.h>

// ---------------------------------------------------------------------------
// Scratch (static device globals — no runtime allocation)
// ---------------------------------------------------------------------------
__device__ float g_h0 [8192u * 2048u];   // layer0 h, full precision
__device__ float g_h0r[8192u * 2048u];   // layer0 h, tf32-rounded (GEMM-A)
__device__ float g_h1r[8192u * 1024u];   // layer1 h, tf32-rounded (GEMM-A)
__device__ float g_pre[8192u * 2048u];   // pre-LN buffer, full precision
__device__ float g_err[8192u * 4096u];   // error, tf32-rounded (GEMM-A)
__device__ float g_xr [8192u * 4096u];   // x, tf32-rounded (GEMM-A)
__device__ float g_wts[20u * 1024u * 1024u]; // rounded weights (see offsets below)
__device__ float g_prec2[4096];

// weight offsets in g_wts (floats)
#define W_GEN0 0u                       // 4096*2048 = 8M
#define W_REC0 (8u*1024u*1024u)         // 2048*4096 = 8M
#define W_GEN1 (16u*1024u*1024u)        // 2048*1024 = 2M
#define W_REC1 (18u*1024u*1024u)        // 1024*2048 = 2M

// ---------------------------------------------------------------------------
// Helpers
// ---------------------------------------------------------------------------
__device__ __forceinline__ uint32_t f2tf32(float x) {
    uint32_t r;
    asm("cvt.rna.tf32.f32 %0, %1;" : "=r"(r) : "f"(x));
    return r;
}
__device__ __forceinline__ float roundtf(float x) {
    return __uint_as_float(f2tf32(x));
}

__device__ __forceinline__ void mma_tf32(float* c, const uint32_t* a, const uint32_t* b) {
    asm volatile(
        "mma.sync.aligned.m16n8k8.row.col.f32.tf32.tf32.f32 "
        "{%0,%1,%2,%3}, {%4,%5,%6,%7}, {%8,%9}, {%0,%1,%2,%3};\n"
        : "+f"(c[0]), "+f"(c[1]), "+f"(c[2]), "+f"(c[3])
        : "r"(a[0]), "r"(a[1]), "r"(a[2]), "r"(a[3]), "r"(b[0]), "r"(b[1]));
}

__device__ __forceinline__ void cp16(uint32_t dst_smem, const void* src) {
    asm volatile("cp.async.cg.shared.global [%0], [%1], 16;" :: "r"(dst_smem), "l"(src));
}
__device__ __forceinline__ void cp_commit() {
    asm volatile("cp.async.commit_group;");
}
template <int N>
__device__ __forceinline__ void cp_wait() {
    asm volatile("cp.async.wait_group %0;" :: "n"(N));
}

// ---------------------------------------------------------------------------
// Elementwise tf32 rounding (for weights and x), float4 vectorized
// ---------------------------------------------------------------------------
__global__ void __launch_bounds__(256) round_kernel(
    const float* __restrict__ in, float* __restrict__ out, int n4)
{
    int i = blockIdx.x * blockDim.x + threadIdx.x;
    if (i < n4) {
        float4 v = reinterpret_cast<const float4*>(in)[i];
        float4 o;
        o.x = roundtf(v.x); o.y = roundtf(v.y);
        o.z = roundtf(v.z); o.w = roundtf(v.w);
        reinterpret_cast<float4*>(out)[i] = o;
    }
}

// ---------------------------------------------------------------------------
// prec2 = softplus(log_prec)^2
// ---------------------------------------------------------------------------
__global__ void prec2_kernel(const float* __restrict__ lp, float* __restrict__ out, int n) {
    int i = blockIdx.x * blockDim.x + threadIdx.x;
    if (i < n) {
        float v = lp[i];
        float sp = (v > 20.f) ? v : log1pf(expf(v));
        out[i] = sp * sp;
    }
}

// ---------------------------------------------------------------------------
// Row LayerNorm. Writes full-precision dst and tf32-rounded dstr.
// ---------------------------------------------------------------------------
template <int H>
__global__ void __launch_bounds__(256) ln_kernel(
    const float* __restrict__ src, float* __restrict__ dst, float* __restrict__ dstr,
    const float* __restrict__ gam, const float* __restrict__ bet)
{
    constexpr int V = H / (4 * 256);
    int row = blockIdx.x;
    const float4* s = reinterpret_cast<const float4*>(src + (size_t)row * H);
    float4* d  = reinterpret_cast<float4*>(dst  + (size_t)row * H);
    float4* dr = reinterpret_cast<float4*>(dstr + (size_t)row * H);

    float4 v[V];
    float sum = 0.f, sq = 0.f;
#pragma unroll
    for (int i = 0; i < V; i++) {
        v[i] = s[threadIdx.x + i * 256];
        sum += v[i].x + v[i].y + v[i].z + v[i].w;
        sq  += v[i].x * v[i].x + v[i].y * v[i].y + v[i].z * v[i].z + v[i].w * v[i].w;
    }
#pragma unroll
    for (int o = 16; o > 0; o >>= 1) {
        sum += __shfl_xor_sync(0xffffffffu, sum, o);
        sq  += __shfl_xor_sync(0xffffffffu, sq,  o);
    }
    __shared__ float sS[8], sQ[8];
    int w = threadIdx.x >> 5, l = threadIdx.x & 31;
    if (l == 0) { sS[w] = sum; sQ[w] = sq; }
    __syncthreads();
    if (threadIdx.x == 0) {
        float ts = 0.f, tq = 0.f;
#pragma unroll
        for (int i = 0; i < 8; i++) { ts += sS[i]; tq += sQ[i]; }
        sS[0] = ts; sQ[0] = tq;
    }
    __syncthreads();
    float mu  = sS[0] * (1.f / H);
    float var = sQ[0] * (1.f / H) - mu * mu;
    float inv = rsqrtf(var + 1e-5f);
#pragma unroll
    for (int i = 0; i < V; i++) {
        int ci = threadIdx.x + i * 256;
        float4 g4 = reinterpret_cast<const float4*>(gam)[ci];
        float4 b4 = reinterpret_cast<const float4*>(bet)[ci];
        float4 o;
        o.x = (v[i].x - mu) * inv * g4.x + b4.x;
        o.y = (v[i].y - mu) * inv * g4.y + b4.y;
        o.z = (v[i].z - mu) * inv * g4.z + b4.z;
        o.w = (v[i].w - mu) * inv * g4.w + b4.w;
        d[ci] = o;
        float4 r;
        r.x = roundtf(o.x); r.y = roundtf(o.y);
        r.z = roundtf(o.z); r.w = roundtf(o.w);
        dr[ci] = r;
    }
}

// ---------------------------------------------------------------------------
// TF32 tensor-core GEMM, 128x128 tile, BK=16, 4-stage cp.async pipeline.
// All A/W inputs are ALREADY tf32-rounded -> no cvt in the mainloop.
//   BT=true : B(k,n) = W[n,k]   (W row-major [N,K])
//   BT=false: B(k,n) = W[k,n]   (W row-major [K,N])
// MODE 0: out = acc + bias[n]
// MODE 1: out = roundtf((X - (acc + bias[n])) * prec2[n])   (err, GEMM-A consumer)
// MODE 2: out = X + 0.2f * acc
// Requires M%128==0, N%128==0, K%16==0.
// ---------------------------------------------------------------------------
template <bool BT, int MODE>
__global__ void __launch_bounds__(256, 2) gemm_tf32(
    const float* __restrict__ A, const float* __restrict__ W,
    const float* __restrict__ bias, const float* __restrict__ X,
    const float* __restrict__ prec2, float* __restrict__ OUT,
    int M, int N, int K)
{
    constexpr int S    = 4;      // pipeline stages
    constexpr int AROW = 20;     // 16 k-floats + 4 pad
    constexpr int BRN  = 136;    // NN path: 128 n-floats + 8 pad
    constexpr int A_FLOATS = 128 * AROW;
    constexpr int B_FLOATS = BT ? 128 * AROW : 16 * BRN;

    extern __shared__ float sm[];
    float* Asm = sm;                       // [S][128][AROW]
    float* Bsm = sm + S * A_FLOATS;

    const uint32_t sA = (uint32_t)__cvta_generic_to_shared(Asm);
    const uint32_t sB = (uint32_t)__cvta_generic_to_shared(Bsm);

    const int tid  = threadIdx.x;
    const int lane = tid & 31;
    const int warp = tid >> 5;
    const int wm = warp >> 2;
    const int wn = warp & 3;
    const int gid = lane >> 2, tig = lane & 3;
    const int M0 = blockIdx.y * 128, N0 = blockIdx.x * 128;

    float acc[4][4][4];
#pragma unroll
    for (int i = 0; i < 4; i++)
#pragma unroll
        for (int j = 0; j < 4; j++)
#pragma unroll
            for (int k = 0; k < 4; k++) acc[i][j][k] = 0.f;

    const int KT = K / 16;

    auto ldgsts = [&](int kt, int st) {
#pragma unroll
        for (int i = 0; i < 2; i++) {
            int c   = tid + 256 * i;
            int row = c >> 2, kv = c & 3;
            cp16(sA + (uint32_t)(st * A_FLOATS + row * AROW + kv * 4) * 4u,
                 A + (size_t)(M0 + row) * K + kt * 16 + kv * 4);
        }
        if (BT) {
#pragma unroll
            for (int i = 0; i < 2; i++) {
                int c   = tid + 256 * i;
                int row = c >> 2, kv = c & 3;
                cp16(sB + (uint32_t)(st * B_FLOATS + row * AROW + kv * 4) * 4u,
                     W + (size_t)(N0 + row) * K + kt * 16 + kv * 4);
            }
        } else {
#pragma unroll
            for (int i = 0; i < 2; i++) {
                int c  = tid + 256 * i;
                int kr = c >> 5, nv = c & 31;
                cp16(sB + (uint32_t)(st * B_FLOATS + kr * BRN + nv * 4) * 4u,
                     W + (size_t)(kt * 16 + kr) * N + N0 + nv * 4);
            }
        }
    };

    // prologue: fill S-1 stages
#pragma unroll
    for (int s = 0; s < S - 1; s++) {
        ldgsts(s, s);
        cp_commit();
    }

    // single-barrier mainloop:
    //   barrier at top orders (a) stage-kt data visible, (b) all warps done
    //   with stage (kt-1)%S, which this iteration's ldgsts overwrites.
    for (int kt = 0; kt < KT; kt++) {
        cp_wait<S - 2>();
        __syncthreads();

        int nk = kt + S - 1;
        if (nk < KT) ldgsts(nk, nk & (S - 1));
        cp_commit();

        const uint32_t* Ast = (const uint32_t*)(Asm + (kt & (S - 1)) * A_FLOATS);
        const uint32_t* Bst = (const uint32_t*)(Bsm + (kt & (S - 1)) * B_FLOATS);

#pragma unroll
        for (int ks = 0; ks < 2; ks++) {
            const int k0 = ks * 8;
            uint32_t af[4][4], bf[4][2];
#pragma unroll
            for (int mm = 0; mm < 4; mm++) {
                int r = wm * 64 + mm * 16 + gid;
                af[mm][0] = Ast[(r    ) * AROW + k0 + tig    ];
                af[mm][1] = Ast[(r + 8) * AROW + k0 + tig    ];
                af[mm][2] = Ast[(r    ) * AROW + k0 + tig + 4];
                af[mm][3] = Ast[(r + 8) * AROW + k0 + tig + 4];
            }
#pragma unroll
            for (int nn = 0; nn < 4; nn++) {
                int cN = wn * 32 + nn * 8 + gid;
                if (BT) {
                    bf[nn][0] = Bst[cN * AROW + k0 + tig    ];
                    bf[nn][1] = Bst[cN * AROW + k0 + tig + 4];
                } else {
                    bf[nn][0] = Bst[(k0 + tig    ) * BRN + cN];
                    bf[nn][1] = Bst[(k0 + tig + 4) * BRN + cN];
                }
            }
#pragma unroll
            for (int mm = 0; mm < 4; mm++)
#pragma unroll
                for (int nn = 0; nn < 4; nn++)
                    mma_tf32(acc[mm][nn], af[mm], bf[nn]);
        }
    }

    // epilogue
#pragma unroll
    for (int mm = 0; mm < 4; mm++) {
        int r0 = M0 + wm * 64 + mm * 16 + gid;
#pragma unroll
        for (int nn = 0; nn < 4; nn++) {
            int c = N0 + wn * 32 + nn * 8 + 2 * tig;
#pragma unroll
            for (int h = 0; h < 2; h++) {
                int r = r0 + h * 8;
                size_t off = (size_t)r * N + c;
                float v0 = acc[mm][nn][2 * h + 0];
                float v1 = acc[mm][nn][2 * h + 1];
                if (MODE == 0) {
                    v0 += bias[c];
                    v1 += bias[c + 1];
                } else if (MODE == 1) {
                    float2 xv = *(const float2*)(X + off);
                    v0 = roundtf((xv.x - (v0 + bias[c]))     * prec2[c]);
                    v1 = roundtf((xv.y - (v1 + bias[c + 1])) * prec2[c + 1]);
                } else {
                    float2 xv = *(const float2*)(X + off);
                    v0 = xv.x + 0.2f * v0;
                    v1 = xv.y + 0.2f * v1;
                }
                float2 o; o.x = v0; o.y = v1;
                *(float2*)(OUT + off) = o;
            }
        }
    }
}

// ---------------------------------------------------------------------------
// Launch sequence (graph-capturable: kernel launches only)
// ---------------------------------------------------------------------------
extern "C" void kernel_launch(void* const* d_in, const int* in_sizes, int n_in,
                              void* d_out, int out_size)
{
    const float* x      = (const float*)d_in[0];
    const float* gen_w0 = (const float*)d_in[1];
    const float* gen_b0 = (const float*)d_in[2];
    const float* rec_w0 = (const float*)d_in[3];
    const float* rec_b0 = (const float*)d_in[4];
    const float* lp0    = (const float*)d_in[5];
    const float* ln_g0  = (const float*)d_in[6];
    const float* ln_b0  = (const float*)d_in[7];
    const float* gen_w1 = (const float*)d_in[8];
    const float* gen_b1 = (const float*)d_in[9];
    const float* rec_w1 = (const float*)d_in[10];
    const float* rec_b1 = (const float*)d_in[11];
    const float* lp1    = (const float*)d_in[12];
    const float* ln_g1  = (const float*)d_in[13];
    const float* ln_b1  = (const float*)d_in[14];
    float* out = (float*)d_out;

    float *h0, *h0r, *h1r, *pre, *err, *xr, *wts, *pr2;
    cudaGetSymbolAddress((void**)&h0,  g_h0);
    cudaGetSymbolAddress((void**)&h0r, g_h0r);
    cudaGetSymbolAddress((void**)&h1r, g_h1r);
    cudaGetSymbolAddress((void**)&pre, g_pre);
    cudaGetSymbolAddress((void**)&err, g_err);
    cudaGetSymbolAddress((void**)&xr,  g_xr);
    cudaGetSymbolAddress((void**)&wts, g_wts);
    cudaGetSymbolAddress((void**)&pr2, g_prec2);

    float* gen_w0r = wts + W_GEN0;
    float* rec_w0r = wts + W_REC0;
    float* gen_w1r = wts + W_GEN1;
    float* rec_w1r = wts + W_REC1;

    const int SM_BT = 4 * 128 * 20 * 2 * 4;              // 81920 B
    const int SM_NN = 4 * (128 * 20 + 16 * 136) * 4;     // 75776 B
    cudaFuncSetAttribute(gemm_tf32<true, 0>,  cudaFuncAttributeMaxDynamicSharedMemorySize, SM_BT);
    cudaFuncSetAttribute(gemm_tf32<true, 1>,  cudaFuncAttributeMaxDynamicSharedMemorySize, SM_BT);
    cudaFuncSetAttribute(gemm_tf32<false, 2>, cudaFuncAttributeMaxDynamicSharedMemorySize, SM_NN);

    const int B = 8192;
    dim3 blk(256);

    // one-time rounding of weights and x (bit-identical to consume-side cvt)
    round_kernel<<<(4096 * 2048 / 4) / 256, blk>>>(gen_w0, gen_w0r, 4096 * 2048 / 4);
    round_kernel<<<(2048 * 4096 / 4) / 256, blk>>>(rec_w0, rec_w0r, 2048 * 4096 / 4);
    round_kernel<<<(2048 * 1024 / 4) / 256, blk>>>(gen_w1, gen_w1r, 2048 * 1024 / 4);
    round_kernel<<<(1024 * 2048 / 4) / 256, blk>>>(rec_w1, rec_w1r, 1024 * 2048 / 4);
    round_kernel<<<(B * 4096 / 4) / 256, blk>>>(x, xr, B * 4096 / 4);

    // ---- layer 0: in=4096, hid=2048 ----
    prec2_kernel<<<4096 / 256, blk>>>(lp0, pr2, 4096);
    gemm_tf32<true, 0><<<dim3(2048 / 128, B / 128), blk, SM_BT>>>(
        xr, rec_w0r, rec_b0, nullptr, nullptr, pre, B, 2048, 4096);
    ln_kernel<2048><<<B, blk>>>(pre, h0, h0r, ln_g0, ln_b0);
    for (int it = 0; it < 3; it++) {
        gemm_tf32<true, 1><<<dim3(4096 / 128, B / 128), blk, SM_BT>>>(
            h0r, gen_w0r, gen_b0, x, pr2, err, B, 4096, 2048);
        gemm_tf32<false, 2><<<dim3(2048 / 128, B / 128), blk, SM_NN>>>(
            err, gen_w0r, nullptr, h0, nullptr, pre, B, 2048, 4096);
        ln_kernel<2048><<<B, blk>>>(pre, h0, h0r, ln_g0, ln_b0);
    }

    // ---- layer 1: in=2048, hid=1024 ----
    prec2_kernel<<<2048 / 256, blk>>>(lp1, pr2, 2048);
    gemm_tf32<true, 0><<<dim3(1024 / 128, B / 128), blk, SM_BT>>>(
        h0r, rec_w1r, rec_b1, nullptr, nullptr, pre, B, 1024, 2048);
    ln_kernel<1024><<<B, blk>>>(pre, out, h1r, ln_g1, ln_b1);
    for (int it = 0; it < 3; it++) {
        gemm_tf32<true, 1><<<dim3(2048 / 128, B / 128), blk, SM_BT>>>(
            h1r, gen_w1r, gen_b1, h0, pr2, err, B, 2048, 1024);
        gemm_tf32<false, 2><<<dim3(1024 / 128, B / 128), blk, SM_NN>>>(
            err, gen_w1r, nullptr, out, nullptr, pre, B, 1024, 2048);
        ln_kernel<1024><<<B, blk>>>(pre, out, h1r, ln_g1, ln_b1);
    }
}

// round 8
// speedup vs baseline: 2.0133x; 1.0666x over previous
#include <cuda_runtime.h>
#include <cstdint>
#include <math.h>

// ---------------------------------------------------------------------------
// Scratch (static device globals — no runtime allocation)
// ---------------------------------------------------------------------------
__device__ float g_h0 [8192u * 2048u];   // layer0 h, full precision
__device__ float g_h0r[8192u * 2048u];   // layer0 h, tf32-rounded
__device__ float g_h1r[8192u * 1024u];   // layer1 h, tf32-rounded
__device__ float g_pre[8192u * 2048u];   // pre-LN buffer
__device__ float g_err[8192u * 4096u];   // error, tf32-rounded
__device__ float g_xr [8192u * 4096u];   // x, tf32-rounded
__device__ float g_wts[20u * 1024u * 1024u]; // rounded weights
__device__ float g_prec2[4096];

#define W_GEN0 0u                       // 4096*2048
#define W_REC0 (8u*1024u*1024u)         // 2048*4096
#define W_GEN1 (16u*1024u*1024u)        // 2048*1024
#define W_REC1 (18u*1024u*1024u)        // 1024*2048

// ---------------------------------------------------------------------------
// Helpers
// ---------------------------------------------------------------------------
__device__ __forceinline__ uint32_t f2tf32(float x) {
    uint32_t r;
    asm("cvt.rna.tf32.f32 %0, %1;" : "=r"(r) : "f"(x));
    return r;
}
__device__ __forceinline__ float roundtf(float x) { return __uint_as_float(f2tf32(x)); }

__device__ __forceinline__ void mma_tf32(float* c, const uint32_t* a, const uint32_t* b) {
    asm volatile(
        "mma.sync.aligned.m16n8k8.row.col.f32.tf32.tf32.f32 "
        "{%0,%1,%2,%3}, {%4,%5,%6,%7}, {%8,%9}, {%0,%1,%2,%3};\n"
        : "+f"(c[0]), "+f"(c[1]), "+f"(c[2]), "+f"(c[3])
        : "r"(a[0]), "r"(a[1]), "r"(a[2]), "r"(a[3]), "r"(b[0]), "r"(b[1]));
}

__device__ __forceinline__ void cp16(uint32_t dst_smem, const void* src) {
    asm volatile("cp.async.cg.shared.global [%0], [%1], 16;" :: "r"(dst_smem), "l"(src));
}
__device__ __forceinline__ void cp_commit() { asm volatile("cp.async.commit_group;"); }
template <int N>
__device__ __forceinline__ void cp_wait() { asm volatile("cp.async.wait_group %0;" :: "n"(N)); }

// ---------------------------------------------------------------------------
// Elementwise tf32 rounding (weights, x)
// ---------------------------------------------------------------------------
__global__ void __launch_bounds__(256) round_kernel(
    const float* __restrict__ in, float* __restrict__ out, int n4)
{
    int i = blockIdx.x * blockDim.x + threadIdx.x;
    if (i < n4) {
        float4 v = reinterpret_cast<const float4*>(in)[i];
        float4 o;
        o.x = roundtf(v.x); o.y = roundtf(v.y);
        o.z = roundtf(v.z); o.w = roundtf(v.w);
        reinterpret_cast<float4*>(out)[i] = o;
    }
}

// ---------------------------------------------------------------------------
// prec2 = softplus(log_prec)^2
// ---------------------------------------------------------------------------
__global__ void prec2_kernel(const float* __restrict__ lp, float* __restrict__ out, int n) {
    int i = blockIdx.x * blockDim.x + threadIdx.x;
    if (i < n) {
        float v = lp[i];
        float sp = (v > 20.f) ? v : log1pf(expf(v));
        out[i] = sp * sp;
    }
}

// ---------------------------------------------------------------------------
// Row LayerNorm. Writes full-precision dst and tf32-rounded dstr.
// ---------------------------------------------------------------------------
template <int H>
__global__ void __launch_bounds__(256) ln_kernel(
    const float* __restrict__ src, float* __restrict__ dst, float* __restrict__ dstr,
    const float* __restrict__ gam, const float* __restrict__ bet)
{
    constexpr int V = H / (4 * 256);
    int row = blockIdx.x;
    const float4* s = reinterpret_cast<const float4*>(src + (size_t)row * H);
    float4* d  = reinterpret_cast<float4*>(dst  + (size_t)row * H);
    float4* dr = reinterpret_cast<float4*>(dstr + (size_t)row * H);

    float4 v[V];
    float sum = 0.f, sq = 0.f;
#pragma unroll
    for (int i = 0; i < V; i++) {
        v[i] = s[threadIdx.x + i * 256];
        sum += v[i].x + v[i].y + v[i].z + v[i].w;
        sq  += v[i].x * v[i].x + v[i].y * v[i].y + v[i].z * v[i].z + v[i].w * v[i].w;
    }
#pragma unroll
    for (int o = 16; o > 0; o >>= 1) {
        sum += __shfl_xor_sync(0xffffffffu, sum, o);
        sq  += __shfl_xor_sync(0xffffffffu, sq,  o);
    }
    __shared__ float sS[8], sQ[8];
    int w = threadIdx.x >> 5, l = threadIdx.x & 31;
    if (l == 0) { sS[w] = sum; sQ[w] = sq; }
    __syncthreads();
    if (threadIdx.x == 0) {
        float ts = 0.f, tq = 0.f;
#pragma unroll
        for (int i = 0; i < 8; i++) { ts += sS[i]; tq += sQ[i]; }
        sS[0] = ts; sQ[0] = tq;
    }
    __syncthreads();
    float mu  = sS[0] * (1.f / H);
    float var = sQ[0] * (1.f / H) - mu * mu;
    float inv = rsqrtf(var + 1e-5f);
#pragma unroll
    for (int i = 0; i < V; i++) {
        int ci = threadIdx.x + i * 256;
        float4 g4 = reinterpret_cast<const float4*>(gam)[ci];
        float4 b4 = reinterpret_cast<const float4*>(bet)[ci];
        float4 o;
        o.x = (v[i].x - mu) * inv * g4.x + b4.x;
        o.y = (v[i].y - mu) * inv * g4.y + b4.y;
        o.z = (v[i].z - mu) * inv * g4.z + b4.z;
        o.w = (v[i].w - mu) * inv * g4.w + b4.w;
        d[ci] = o;
        float4 r;
        r.x = roundtf(o.x); r.y = roundtf(o.y);
        r.z = roundtf(o.z); r.w = roundtf(o.w);
        dr[ci] = r;
    }
}

// ---------------------------------------------------------------------------
// TF32 mma.sync GEMM, 128x128 tile, BK=32 stages, 3-stage cp.async pipeline.
// Inputs pre-rounded to tf32 -> mainloop is pure LDS+MMA.
//   BT=true : B(k,n) = W[n,k]   (W row-major [N,K])
//   BT=false: B(k,n) = W[k,n]   (W row-major [K,N])
// MODE 0: out = acc + bias[n]
// MODE 1: out = roundtf((X - (acc + bias[n])) * prec2[n])
// MODE 2: out = X + 0.2f * acc
// Requires M%128==0, N%128==0, K%32==0.
// ---------------------------------------------------------------------------
template <bool BT, int MODE>
__global__ void __launch_bounds__(256, 2) gemm_tf32(
    const float* __restrict__ A, const float* __restrict__ W,
    const float* __restrict__ bias, const float* __restrict__ X,
    const float* __restrict__ prec2, float* __restrict__ OUT,
    int M, int N, int K)
{
    constexpr int S    = 3;      // pipeline stages
    constexpr int AROW = 36;     // 32 k-floats + 4 pad (144B rows, 16B aligned)
    constexpr int BRN  = 136;    // NN path: 128 n-floats + 8 pad
    constexpr int A_FLOATS = 128 * AROW;            // 4608 per stage
    constexpr int B_FLOATS = BT ? 128 * AROW : 32 * BRN;

    extern __shared__ float sm[];
    float* Asm = sm;                       // [S][128][AROW]
    float* Bsm = sm + S * A_FLOATS;

    const uint32_t sA = (uint32_t)__cvta_generic_to_shared(Asm);
    const uint32_t sB = (uint32_t)__cvta_generic_to_shared(Bsm);

    const int tid  = threadIdx.x;
    const int lane = tid & 31;
    const int warp = tid >> 5;
    const int wm = warp >> 2;
    const int wn = warp & 3;
    const int gid = lane >> 2, tig = lane & 3;
    const int M0 = blockIdx.y * 128, N0 = blockIdx.x * 128;

    float acc[4][4][4];
#pragma unroll
    for (int i = 0; i < 4; i++)
#pragma unroll
        for (int j = 0; j < 4; j++)
#pragma unroll
            for (int k = 0; k < 4; k++) acc[i][j][k] = 0.f;

    const int KT = K / 32;

    // one stage = 128 rows x 32 floats for A (1024 cp16 = 4/thread), same for B
    auto ldgsts = [&](int kt, int st) {
#pragma unroll
        for (int i = 0; i < 4; i++) {
            int c   = tid + 256 * i;           // 0..1023
            int row = c >> 3, kv = c & 7;
            cp16(sA + (uint32_t)(st * A_FLOATS + row * AROW + kv * 4) * 4u,
                 A + (size_t)(M0 + row) * K + kt * 32 + kv * 4);
        }
        if (BT) {
#pragma unroll
            for (int i = 0; i < 4; i++) {
                int c   = tid + 256 * i;
                int row = c >> 3, kv = c & 7;
                cp16(sB + (uint32_t)(st * B_FLOATS + row * AROW + kv * 4) * 4u,
                     W + (size_t)(N0 + row) * K + kt * 32 + kv * 4);
            }
        } else {
#pragma unroll
            for (int i = 0; i < 4; i++) {
                int c  = tid + 256 * i;
                int kr = c >> 5, nv = c & 31;  // k-row 0..31, nvec 0..31
                cp16(sB + (uint32_t)(st * B_FLOATS + kr * BRN + nv * 4) * 4u,
                     W + (size_t)(kt * 32 + kr) * N + N0 + nv * 4);
            }
        }
    };

    // prologue: fill S-1 = 2 stages
    ldgsts(0, 0); cp_commit();
    ldgsts(1, 1); cp_commit();

    // single-barrier mainloop: barrier at top of iter kt orders (a) stage-kt
    // data visible, (b) all warps done with stage (kt-1)%S, which this
    // iteration's ldgsts (for kt+2) overwrites.
    for (int kt = 0; kt < KT; kt++) {
        cp_wait<1>();
        __syncthreads();

        int nk = kt + 2;
        if (nk < KT) ldgsts(nk, nk % S);
        cp_commit();

        const uint32_t* Ast = (const uint32_t*)(Asm + (kt % S) * A_FLOATS);
        const uint32_t* Bst = (const uint32_t*)(Bsm + (kt % S) * B_FLOATS);

#pragma unroll
        for (int ks = 0; ks < 4; ks++) {
            const int k0 = ks * 8;
            uint32_t af[4][4], bf[4][2];
#pragma unroll
            for (int mm = 0; mm < 4; mm++) {
                int r = wm * 64 + mm * 16 + gid;
                af[mm][0] = Ast[(r    ) * AROW + k0 + tig    ];
                af[mm][1] = Ast[(r + 8) * AROW + k0 + tig    ];
                af[mm][2] = Ast[(r    ) * AROW + k0 + tig + 4];
                af[mm][3] = Ast[(r + 8) * AROW + k0 + tig + 4];
            }
#pragma unroll
            for (int nn = 0; nn < 4; nn++) {
                int cN = wn * 32 + nn * 8 + gid;
                if (BT) {
                    bf[nn][0] = Bst[cN * AROW + k0 + tig    ];
                    bf[nn][1] = Bst[cN * AROW + k0 + tig + 4];
                } else {
                    bf[nn][0] = Bst[(k0 + tig    ) * BRN + cN];
                    bf[nn][1] = Bst[(k0 + tig + 4) * BRN + cN];
                }
            }
#pragma unroll
            for (int mm = 0; mm < 4; mm++)
#pragma unroll
                for (int nn = 0; nn < 4; nn++)
                    mma_tf32(acc[mm][nn], af[mm], bf[nn]);
        }
    }

    // epilogue
#pragma unroll
    for (int mm = 0; mm < 4; mm++) {
        int r0 = M0 + wm * 64 + mm * 16 + gid;
#pragma unroll
        for (int nn = 0; nn < 4; nn++) {
            int c = N0 + wn * 32 + nn * 8 + 2 * tig;
#pragma unroll
            for (int h = 0; h < 2; h++) {
                int r = r0 + h * 8;
                size_t off = (size_t)r * N + c;
                float v0 = acc[mm][nn][2 * h + 0];
                float v1 = acc[mm][nn][2 * h + 1];
                if (MODE == 0) {
                    v0 += bias[c];
                    v1 += bias[c + 1];
                } else if (MODE == 1) {
                    float2 xv = *(const float2*)(X + off);
                    v0 = roundtf((xv.x - (v0 + bias[c]))     * prec2[c]);
                    v1 = roundtf((xv.y - (v1 + bias[c + 1])) * prec2[c + 1]);
                } else {
                    float2 xv = *(const float2*)(X + off);
                    v0 = xv.x + 0.2f * v0;
                    v1 = xv.y + 0.2f * v1;
                }
                float2 o; o.x = v0; o.y = v1;
                *(float2*)(OUT + off) = o;
            }
        }
    }
}

// ---------------------------------------------------------------------------
// Launch sequence (graph-capturable: kernel launches only)
// ---------------------------------------------------------------------------
extern "C" void kernel_launch(void* const* d_in, const int* in_sizes, int n_in,
                              void* d_out, int out_size)
{
    const float* x      = (const float*)d_in[0];
    const float* gen_w0 = (const float*)d_in[1];
    const float* gen_b0 = (const float*)d_in[2];
    const float* rec_w0 = (const float*)d_in[3];
    const float* rec_b0 = (const float*)d_in[4];
    const float* lp0    = (const float*)d_in[5];
    const float* ln_g0  = (const float*)d_in[6];
    const float* ln_b0  = (const float*)d_in[7];
    const float* gen_w1 = (const float*)d_in[8];
    const float* gen_b1 = (const float*)d_in[9];
    const float* rec_w1 = (const float*)d_in[10];
    const float* rec_b1 = (const float*)d_in[11];
    const float* lp1    = (const float*)d_in[12];
    const float* ln_g1  = (const float*)d_in[13];
    const float* ln_b1  = (const float*)d_in[14];
    float* out = (float*)d_out;

    float *h0, *h0r, *h1r, *pre, *err, *xr, *wts, *pr2;
    cudaGetSymbolAddress((void**)&h0,  g_h0);
    cudaGetSymbolAddress((void**)&h0r, g_h0r);
    cudaGetSymbolAddress((void**)&h1r, g_h1r);
    cudaGetSymbolAddress((void**)&pre, g_pre);
    cudaGetSymbolAddress((void**)&err, g_err);
    cudaGetSymbolAddress((void**)&xr,  g_xr);
    cudaGetSymbolAddress((void**)&wts, g_wts);
    cudaGetSymbolAddress((void**)&pr2, g_prec2);

    float* gen_w0r = wts + W_GEN0;
    float* rec_w0r = wts + W_REC0;
    float* gen_w1r = wts + W_GEN1;
    float* rec_w1r = wts + W_REC1;

    // dynamic smem: BT = 3*(4608*2)*4 = 110,592 B; NN = 3*(4608+4352)*4 = 107,520 B
    const int SM_BT = 3 * (128 * 36 * 2) * 4;
    const int SM_NN = 3 * (128 * 36 + 32 * 136) * 4;
    cudaFuncSetAttribute(gemm_tf32<true, 0>,  cudaFuncAttributeMaxDynamicSharedMemorySize, SM_BT);
    cudaFuncSetAttribute(gemm_tf32<true, 1>,  cudaFuncAttributeMaxDynamicSharedMemorySize, SM_BT);
    cudaFuncSetAttribute(gemm_tf32<false, 2>, cudaFuncAttributeMaxDynamicSharedMemorySize, SM_NN);

    const int B = 8192;
    dim3 blk(256);

    // one-time rounding of weights and x (bit-identical to consume-side cvt)
    round_kernel<<<(4096 * 2048 / 4) / 256, blk>>>(gen_w0, gen_w0r, 4096 * 2048 / 4);
    round_kernel<<<(2048 * 4096 / 4) / 256, blk>>>(rec_w0, rec_w0r, 2048 * 4096 / 4);
    round_kernel<<<(2048 * 1024 / 4) / 256, blk>>>(gen_w1, gen_w1r, 2048 * 1024 / 4);
    round_kernel<<<(1024 * 2048 / 4) / 256, blk>>>(rec_w1, rec_w1r, 1024 * 2048 / 4);
    round_kernel<<<(B * 4096 / 4) / 256, blk>>>(x, xr, B * 4096 / 4);

    // ---- layer 0: in=4096, hid=2048 ----
    prec2_kernel<<<4096 / 256, blk>>>(lp0, pr2, 4096);
    gemm_tf32<true, 0><<<dim3(2048 / 128, B / 128), blk, SM_BT>>>(
        xr, rec_w0r, rec_b0, nullptr, nullptr, pre, B, 2048, 4096);
    ln_kernel<2048><<<B, blk>>>(pre, h0, h0r, ln_g0, ln_b0);
    for (int it = 0; it < 3; it++) {
        gemm_tf32<true, 1><<<dim3(4096 / 128, B / 128), blk, SM_BT>>>(
            h0r, gen_w0r, gen_b0, x, pr2, err, B, 4096, 2048);
        gemm_tf32<false, 2><<<dim3(2048 / 128, B / 128), blk, SM_NN>>>(
            err, gen_w0r, nullptr, h0, nullptr, pre, B, 2048, 4096);
        ln_kernel<2048><<<B, blk>>>(pre, h0, h0r, ln_g0, ln_b0);
    }

    // ---- layer 1: in=2048, hid=1024 ----
    prec2_kernel<<<2048 / 256, blk>>>(lp1, pr2, 2048);
    gemm_tf32<true, 0><<<dim3(1024 / 128, B / 128), blk, SM_BT>>>(
        h0r, rec_w1r, rec_b1, nullptr, nullptr, pre, B, 1024, 2048);
    ln_kernel<1024><<<B, blk>>>(pre, out, h1r, ln_g1, ln_b1);
    for (int it = 0; it < 3; it++) {
        gemm_tf32<true, 1><<<dim3(2048 / 128, B / 128), blk, SM_BT>>>(
            h1r, gen_w1r, gen_b1, h0, pr2, err, B, 2048, 1024);
        gemm_tf32<false, 2><<<dim3(1024 / 128, B / 128), blk, SM_NN>>>(
            err, gen_w1r, nullptr, out, nullptr, pre, B, 1024, 2048);
        ln_kernel<1024><<<B, blk>>>(pre, out, h1r, ln_g1, ln_b1);
    }
}